// round 5
// baseline (speedup 1.0000x reference)
#include <cuda_runtime.h>

#define NN 100000
#define NE 1600000
#define IND 75
#define H 64
#define HB 16

// Scratch (allocation-free rule: __device__ globals)
__device__ __align__(256) float g_hA[NN * H];
__device__ __align__(256) float g_hB[NN * H];
__device__ __align__(256) float g_P[NN * H];
__device__ __align__(256) float g_agg[NN * H];

// ---- f32x2 packed helpers -------------------------------------------------
typedef unsigned long long u64t;
__device__ __forceinline__ u64t pk2(float lo, float hi) {
    u64t r; asm("mov.b64 %0, {%1, %2};" : "=l"(r) : "f"(lo), "f"(hi)); return r;
}
__device__ __forceinline__ void upk2(u64t v, float& lo, float& hi) {
    asm("mov.b64 {%0, %1}, %2;" : "=f"(lo), "=f"(hi) : "l"(v));
}
__device__ __forceinline__ u64t fma2(u64t a, u64t b, u64t c) {
    u64t d; asm("fma.rn.f32x2 %0, %1, %2, %3;" : "=l"(d) : "l"(a), "l"(b), "l"(c)); return d;
}

// ---------------------------------------------------------------------------
// proj: out = x @ W(75x64) + b     (run once)
// ---------------------------------------------------------------------------
__global__ __launch_bounds__(256) void proj_kernel(const float* __restrict__ x,
                                                   const float* __restrict__ w,
                                                   const float* __restrict__ b,
                                                   float* __restrict__ out) {
    __shared__ float sW[IND][H];
    __shared__ float sA[32][IND + 1];
    for (int i = threadIdx.x; i < IND * H; i += 256) sW[i / H][i % H] = w[i];

    const int lane = threadIdx.x & 31, wid = threadIdx.x >> 5;
    const int nl = lane & 3, cg = lane >> 2;
    const int myn = wid * 4 + nl;
    const float4 bb0 = *(const float4*)&b[cg * 8];
    const float4 bb1 = *(const float4*)&b[cg * 8 + 4];

    for (int tile = blockIdx.x; tile < NN / 32; tile += gridDim.x) {
        const int base = tile * 32;
        __syncthreads();
        for (int i = threadIdx.x; i < 32 * IND; i += 256)
            sA[i / IND][i % IND] = x[(size_t)base * IND + i];
        __syncthreads();

        float acc[8] = {bb0.x, bb0.y, bb0.z, bb0.w, bb1.x, bb1.y, bb1.z, bb1.w};
#pragma unroll 5
        for (int k = 0; k < IND; k++) {
            const float a = sA[myn][k];
            const float4 w0 = *(const float4*)&sW[k][cg * 8];
            const float4 w1 = *(const float4*)&sW[k][cg * 8 + 4];
            acc[0] += a * w0.x; acc[1] += a * w0.y; acc[2] += a * w0.z; acc[3] += a * w0.w;
            acc[4] += a * w1.x; acc[5] += a * w1.y; acc[6] += a * w1.z; acc[7] += a * w1.w;
        }
        const size_t o = (size_t)(base + myn) * H + cg * 8;
        *(float4*)&out[o]     = make_float4(acc[0], acc[1], acc[2], acc[3]);
        *(float4*)&out[o + 4] = make_float4(acc[4], acc[5], acc[6], acc[7]);
    }
}

// ---------------------------------------------------------------------------
// pk: P = h @ W2h(64x64) + b2, and zero agg (fused).
// ---------------------------------------------------------------------------
__global__ __launch_bounds__(256) void pk_kernel(const float* __restrict__ h,
                                                 const float* __restrict__ w,
                                                 const float* __restrict__ b,
                                                 float* __restrict__ P,
                                                 float* __restrict__ agg) {
    __shared__ float sW[H][H];
    __shared__ float sA[32][H + 1];
    for (int i = threadIdx.x; i < H * H; i += 256) sW[i >> 6][i & 63] = w[i];

    const int lane = threadIdx.x & 31, wid = threadIdx.x >> 5;
    const int nl = lane & 3, cg = lane >> 2;
    const int myn = wid * 4 + nl;
    const float4 bb0 = *(const float4*)&b[cg * 8];
    const float4 bb1 = *(const float4*)&b[cg * 8 + 4];
    const float4 z4 = make_float4(0.f, 0.f, 0.f, 0.f);

    for (int tile = blockIdx.x; tile < NN / 32; tile += gridDim.x) {
        const int base = tile * 32;
        __syncthreads();
        for (int i = threadIdx.x; i < 32 * H; i += 256)
            sA[i >> 6][i & 63] = h[(size_t)base * H + i];
        __syncthreads();

        float acc[8] = {bb0.x, bb0.y, bb0.z, bb0.w, bb1.x, bb1.y, bb1.z, bb1.w};
#pragma unroll 8
        for (int k = 0; k < H; k++) {
            const float a = sA[myn][k];
            const float4 w0 = *(const float4*)&sW[k][cg * 8];
            const float4 w1 = *(const float4*)&sW[k][cg * 8 + 4];
            acc[0] += a * w0.x; acc[1] += a * w0.y; acc[2] += a * w0.z; acc[3] += a * w0.w;
            acc[4] += a * w1.x; acc[5] += a * w1.y; acc[6] += a * w1.z; acc[7] += a * w1.w;
        }
        const size_t o = (size_t)(base + myn) * H + cg * 8;
        *(float4*)&P[o]     = make_float4(acc[0], acc[1], acc[2], acc[3]);
        *(float4*)&P[o + 4] = make_float4(acc[4], acc[5], acc[6], acc[7]);
        *(float4*)&agg[o]     = z4;
        *(float4*)&agg[o + 4] = z4;
    }
}

// ---------------------------------------------------------------------------
// edge v3: edge-parallel, atomic scatter, ZERO MIO ops in the hot loop.
// Half-warp per edge (lanes 0-15 -> edge 2p, 16-31 -> edge 2p+1), lane owns
// 4 columns hl*4..hl*4+3. W2e packed over k-pairs in 32 b64 registers;
// edge-attr k-pairs come straight from 2x ulonglong2 loads (the two halves'
// rows are consecutive -> 128B contiguous per warp LDG). Inner loop: 32 FFMA2.
// ---------------------------------------------------------------------------
__global__ __launch_bounds__(256) void edge_kernel(const int* __restrict__ esrc,
                                                   const int* __restrict__ edst,
                                                   const float* __restrict__ eattr,
                                                   const float* __restrict__ w2e,
                                                   const float* __restrict__ P,
                                                   float* __restrict__ agg) {
    const int lane = threadIdx.x & 31;
    const int half = lane >> 4, hl = lane & 15;
    const int cbase = hl * 4;

    // Pack W2e[k][c] over k-pairs: W[j][c] = (w2e[2j][cbase+c], w2e[2j+1][cbase+c])
    u64t W[HB / 2][4];
#pragma unroll
    for (int j = 0; j < HB / 2; j++)
#pragma unroll
        for (int c = 0; c < 4; c++)
            W[j][c] = pk2(w2e[(2 * j) * H + cbase + c],
                          w2e[(2 * j + 1) * H + cbase + c]);

    const int gw = blockIdx.x * 8 + (threadIdx.x >> 5);
    const int nw = gridDim.x * 8;

    for (int p = gw; p < NE / 2; p += nw) {
        const int e = 2 * p + half;
        const int src = esrc[e];
        const int dst = edst[e];
        if ((unsigned)src >= NN || (unsigned)dst >= NN) continue;

        // edge attr row as 8 packed k-pairs (4x LDG.128; warp spans 128B contiguous)
        const ulonglong2* ep = (const ulonglong2*)(eattr + (size_t)e * HB);
        const ulonglong2 u0 = ep[0], u1 = ep[1], u2 = ep[2], u3 = ep[3];

        // P[src] columns for this lane (coalesced float4 across half-warp)
        const float4 pv = *(const float4*)(P + (size_t)src * H + cbase);

        u64t s0 = 0, s1 = 0, s2 = 0, s3 = 0;
        s0 = fma2(u0.x, W[0][0], s0); s1 = fma2(u0.x, W[0][1], s1);
        s2 = fma2(u0.x, W[0][2], s2); s3 = fma2(u0.x, W[0][3], s3);
        s0 = fma2(u0.y, W[1][0], s0); s1 = fma2(u0.y, W[1][1], s1);
        s2 = fma2(u0.y, W[1][2], s2); s3 = fma2(u0.y, W[1][3], s3);
        s0 = fma2(u1.x, W[2][0], s0); s1 = fma2(u1.x, W[2][1], s1);
        s2 = fma2(u1.x, W[2][2], s2); s3 = fma2(u1.x, W[2][3], s3);
        s0 = fma2(u1.y, W[3][0], s0); s1 = fma2(u1.y, W[3][1], s1);
        s2 = fma2(u1.y, W[3][2], s2); s3 = fma2(u1.y, W[3][3], s3);
        s0 = fma2(u2.x, W[4][0], s0); s1 = fma2(u2.x, W[4][1], s1);
        s2 = fma2(u2.x, W[4][2], s2); s3 = fma2(u2.x, W[4][3], s3);
        s0 = fma2(u2.y, W[5][0], s0); s1 = fma2(u2.y, W[5][1], s1);
        s2 = fma2(u2.y, W[5][2], s2); s3 = fma2(u2.y, W[5][3], s3);
        s0 = fma2(u3.x, W[6][0], s0); s1 = fma2(u3.x, W[6][1], s1);
        s2 = fma2(u3.x, W[6][2], s2); s3 = fma2(u3.x, W[6][3], s3);
        s0 = fma2(u3.y, W[7][0], s0); s1 = fma2(u3.y, W[7][1], s1);
        s2 = fma2(u3.y, W[7][2], s2); s3 = fma2(u3.y, W[7][3], s3);

        float lo, hi, m0, m1, m2, m3;
        upk2(s0, lo, hi); m0 = pv.x + (lo + hi);
        upk2(s1, lo, hi); m1 = pv.y + (lo + hi);
        upk2(s2, lo, hi); m2 = pv.z + (lo + hi);
        upk2(s3, lo, hi); m3 = pv.w + (lo + hi);
        m0 = fmaxf(m0, 0.1f * m0);
        m1 = fmaxf(m1, 0.1f * m1);
        m2 = fmaxf(m2, 0.1f * m2);
        m3 = fmaxf(m3, 0.1f * m3);

        float* dp = agg + (size_t)dst * H + cbase;
        asm volatile("red.global.add.v4.f32 [%0], {%1, %2, %3, %4};"
                     :: "l"(dp), "f"(m0), "f"(m1), "f"(m2), "f"(m3)
                     : "memory");
    }
}

// ---------------------------------------------------------------------------
// upd: out = concat(h, agg) @ W1(128x64) + b1
// ---------------------------------------------------------------------------
__global__ __launch_bounds__(256) void upd_kernel(const float* __restrict__ h,
                                                  const float* __restrict__ agg,
                                                  const float* __restrict__ w,
                                                  const float* __restrict__ b,
                                                  float* __restrict__ out) {
    __shared__ float sW[2 * H][H];   // 32768 B
    __shared__ float sA[32][2 * H];  // 16384 B, XOR-swizzled by (row&3)<<3
    for (int i = threadIdx.x; i < 2 * H * H; i += 256) sW[i >> 6][i & 63] = w[i];

    const int lane = threadIdx.x & 31, wid = threadIdx.x >> 5;
    const int nl = lane & 3, cg = lane >> 2;
    const int myn = wid * 4 + nl;
    const int swz = nl << 3;
    const float4 bb0 = *(const float4*)&b[cg * 8];
    const float4 bb1 = *(const float4*)&b[cg * 8 + 4];

    for (int tile = blockIdx.x; tile < NN / 32; tile += gridDim.x) {
        const int base = tile * 32;
        __syncthreads();
        for (int i = threadIdx.x; i < 32 * H; i += 256) {
            const int r = i >> 6, c = i & 63;
            const int s = (r & 3) << 3;
            sA[r][c ^ s]        = h[(size_t)base * H + i];
            sA[r][(c + 64) ^ s] = agg[(size_t)base * H + i];
        }
        __syncthreads();

        float acc[8] = {bb0.x, bb0.y, bb0.z, bb0.w, bb1.x, bb1.y, bb1.z, bb1.w};
#pragma unroll 8
        for (int k = 0; k < 2 * H; k++) {
            const float a = sA[myn][k ^ swz];
            const float4 w0 = *(const float4*)&sW[k][cg * 8];
            const float4 w1 = *(const float4*)&sW[k][cg * 8 + 4];
            acc[0] += a * w0.x; acc[1] += a * w0.y; acc[2] += a * w0.z; acc[3] += a * w0.w;
            acc[4] += a * w1.x; acc[5] += a * w1.y; acc[6] += a * w1.z; acc[7] += a * w1.w;
        }
        const size_t o = (size_t)(base + myn) * H + cg * 8;
        *(float4*)&out[o]     = make_float4(acc[0], acc[1], acc[2], acc[3]);
        *(float4*)&out[o + 4] = make_float4(acc[4], acc[5], acc[6], acc[7]);
    }
}

// ---------------------------------------------------------------------------
extern "C" void kernel_launch(void* const* d_in, const int* in_sizes, int n_in,
                              void* d_out, int out_size) {
    const float* x      = (const float*)d_in[0];   // [100000, 75]
    const int*   eidx   = (const int*)d_in[1];     // [2, 1600000] (int64 -> int32)
    const float* eattr  = (const float*)d_in[2];   // [1600000, 16]
    const float* proj_w = (const float*)d_in[3];
    const float* proj_b = (const float*)d_in[4];
    const float* u2w    = (const float*)d_in[5];   // [3, 80, 64]
    const float* u2b    = (const float*)d_in[6];
    const float* u1w    = (const float*)d_in[7];   // [3, 128, 64]
    const float* u1b    = (const float*)d_in[8];
    float*       out    = (float*)d_out;           // [100000, 64]

    float *hA, *hB, *P, *agg;
    cudaGetSymbolAddress((void**)&hA, g_hA);
    cudaGetSymbolAddress((void**)&hB, g_hB);
    cudaGetSymbolAddress((void**)&P, g_P);
    cudaGetSymbolAddress((void**)&agg, g_agg);

    proj_kernel<<<592, 256>>>(x, proj_w, proj_b, hA);

    for (int l = 0; l < 3; l++) {
        const float* hin = (l == 1) ? hB : hA;          // l0:A, l1:B, l2:A
        float* hout = (l == 0) ? hB : ((l == 1) ? hA : out);
        const float* w2 = u2w + (size_t)l * 80 * 64;     // rows 0..63 = W2h, 64..79 = W2e
        pk_kernel<<<592, 256>>>(hin, w2, u2b + l * 64, P, agg);
        edge_kernel<<<1184, 256>>>(eidx, eidx + NE, eattr, w2 + 64 * 64, P, agg);
        upd_kernel<<<592, 256>>>(hin, agg, u1w + (size_t)l * 128 * 64, u1b + l * 64, hout);
    }
}

// round 6
// speedup vs baseline: 1.1654x; 1.1654x over previous
#include <cuda_runtime.h>

#define NN 100000
#define NE 1600000
#define IND 75
#define H 64
#define HB 16

// Scratch (allocation-free rule: __device__ globals)
__device__ __align__(256) float g_hA[NN * H];
__device__ __align__(256) float g_hB[NN * H];
__device__ __align__(256) float g_P[NN * H];
__device__ __align__(256) float g_agg[NN * H];
__device__ __align__(256) float g_B[(size_t)NE * H];   // eattr @ W2e per layer

// ---------------------------------------------------------------------------
// proj: out = x @ W(75x64) + b     (run once)
// ---------------------------------------------------------------------------
__global__ __launch_bounds__(256) void proj_kernel(const float* __restrict__ x,
                                                   const float* __restrict__ w,
                                                   const float* __restrict__ b,
                                                   float* __restrict__ out) {
    __shared__ float sW[IND][H];
    __shared__ float sA[32][IND + 1];
    for (int i = threadIdx.x; i < IND * H; i += 256) sW[i / H][i % H] = w[i];

    const int lane = threadIdx.x & 31, wid = threadIdx.x >> 5;
    const int nl = lane & 3, cg = lane >> 2;
    const int myn = wid * 4 + nl;
    const float4 bb0 = *(const float4*)&b[cg * 8];
    const float4 bb1 = *(const float4*)&b[cg * 8 + 4];

    for (int tile = blockIdx.x; tile < NN / 32; tile += gridDim.x) {
        const int base = tile * 32;
        __syncthreads();
        for (int i = threadIdx.x; i < 32 * IND; i += 256)
            sA[i / IND][i % IND] = x[(size_t)base * IND + i];
        __syncthreads();

        float acc[8] = {bb0.x, bb0.y, bb0.z, bb0.w, bb1.x, bb1.y, bb1.z, bb1.w};
#pragma unroll 5
        for (int k = 0; k < IND; k++) {
            const float a = sA[myn][k];
            const float4 w0 = *(const float4*)&sW[k][cg * 8];
            const float4 w1 = *(const float4*)&sW[k][cg * 8 + 4];
            acc[0] += a * w0.x; acc[1] += a * w0.y; acc[2] += a * w0.z; acc[3] += a * w0.w;
            acc[4] += a * w1.x; acc[5] += a * w1.y; acc[6] += a * w1.z; acc[7] += a * w1.w;
        }
        const size_t o = (size_t)(base + myn) * H + cg * 8;
        *(float4*)&out[o]     = make_float4(acc[0], acc[1], acc[2], acc[3]);
        *(float4*)&out[o + 4] = make_float4(acc[4], acc[5], acc[6], acc[7]);
    }
}

// ---------------------------------------------------------------------------
// pk: P = h @ W2h(64x64) + b2, and zero agg (fused).
// ---------------------------------------------------------------------------
__global__ __launch_bounds__(256) void pk_kernel(const float* __restrict__ h,
                                                 const float* __restrict__ w,
                                                 const float* __restrict__ b,
                                                 float* __restrict__ P,
                                                 float* __restrict__ agg) {
    __shared__ float sW[H][H];
    __shared__ float sA[32][H + 1];
    for (int i = threadIdx.x; i < H * H; i += 256) sW[i >> 6][i & 63] = w[i];

    const int lane = threadIdx.x & 31, wid = threadIdx.x >> 5;
    const int nl = lane & 3, cg = lane >> 2;
    const int myn = wid * 4 + nl;
    const float4 bb0 = *(const float4*)&b[cg * 8];
    const float4 bb1 = *(const float4*)&b[cg * 8 + 4];
    const float4 z4 = make_float4(0.f, 0.f, 0.f, 0.f);

    for (int tile = blockIdx.x; tile < NN / 32; tile += gridDim.x) {
        const int base = tile * 32;
        __syncthreads();
        for (int i = threadIdx.x; i < 32 * H; i += 256)
            sA[i >> 6][i & 63] = h[(size_t)base * H + i];
        __syncthreads();

        float acc[8] = {bb0.x, bb0.y, bb0.z, bb0.w, bb1.x, bb1.y, bb1.z, bb1.w};
#pragma unroll 8
        for (int k = 0; k < H; k++) {
            const float a = sA[myn][k];
            const float4 w0 = *(const float4*)&sW[k][cg * 8];
            const float4 w1 = *(const float4*)&sW[k][cg * 8 + 4];
            acc[0] += a * w0.x; acc[1] += a * w0.y; acc[2] += a * w0.z; acc[3] += a * w0.w;
            acc[4] += a * w1.x; acc[5] += a * w1.y; acc[6] += a * w1.z; acc[7] += a * w1.w;
        }
        const size_t o = (size_t)(base + myn) * H + cg * 8;
        *(float4*)&P[o]     = make_float4(acc[0], acc[1], acc[2], acc[3]);
        *(float4*)&P[o + 4] = make_float4(acc[4], acc[5], acc[6], acc[7]);
        *(float4*)&agg[o]     = z4;
        *(float4*)&agg[o + 4] = z4;
    }
}

// ---------------------------------------------------------------------------
// mm: B = eattr @ W2e(16x64)  [1.6M x 16] -> [1.6M x 64]  (per layer)
// Same tile pattern as proj: 32 edges/block-tile, warp=4 edges, thread=8 cols.
// ---------------------------------------------------------------------------
__global__ __launch_bounds__(256) void mm_kernel(const float* __restrict__ eattr,
                                                 const float* __restrict__ w2e,
                                                 float* __restrict__ B) {
    __shared__ float sW[HB][H];        // 4096 B
    __shared__ float sA[32][HB + 1];   // 2176 B
    for (int i = threadIdx.x; i < HB * H; i += 256) sW[i >> 6][i & 63] = w2e[i];

    const int lane = threadIdx.x & 31, wid = threadIdx.x >> 5;
    const int nl = lane & 3, cg = lane >> 2;
    const int myn = wid * 4 + nl;

    for (int tile = blockIdx.x; tile < NE / 32; tile += gridDim.x) {
        const int base = tile * 32;
        __syncthreads();
        for (int i = threadIdx.x; i < 32 * HB; i += 256)
            sA[i >> 4][i & 15] = eattr[(size_t)base * HB + i];
        __syncthreads();

        float acc[8] = {0.f, 0.f, 0.f, 0.f, 0.f, 0.f, 0.f, 0.f};
#pragma unroll
        for (int k = 0; k < HB; k++) {
            const float a = sA[myn][k];
            const float4 w0 = *(const float4*)&sW[k][cg * 8];
            const float4 w1 = *(const float4*)&sW[k][cg * 8 + 4];
            acc[0] += a * w0.x; acc[1] += a * w0.y; acc[2] += a * w0.z; acc[3] += a * w0.w;
            acc[4] += a * w1.x; acc[5] += a * w1.y; acc[6] += a * w1.z; acc[7] += a * w1.w;
        }
        const size_t o = (size_t)(base + myn) * H + cg * 8;
        *(float4*)&B[o]     = make_float4(acc[0], acc[1], acc[2], acc[3]);
        *(float4*)&B[o + 4] = make_float4(acc[4], acc[5], acc[6], acc[7]);
    }
}

// ---------------------------------------------------------------------------
// edge v4: pure memory: agg[dst] +=red leakyrelu(P[src] + B[e]).
// Half-warp per edge, lane owns 4 cols. Zero MIO, ~25 regs, ~23 issues/2 edges.
// ---------------------------------------------------------------------------
__global__ __launch_bounds__(256) void edge_kernel(const int* __restrict__ esrc,
                                                   const int* __restrict__ edst,
                                                   const float* __restrict__ B,
                                                   const float* __restrict__ P,
                                                   float* __restrict__ agg) {
    const int lane = threadIdx.x & 31;
    const int half = lane >> 4, hl = lane & 15;
    const int cbase = hl * 4;

    const int gw = blockIdx.x * 8 + (threadIdx.x >> 5);
    const int nw = gridDim.x * 8;

    for (int p = gw; p < NE / 2; p += nw) {
        const int e = 2 * p + half;
        const int src = esrc[e];
        const int dst = edst[e];
        if ((unsigned)src >= NN || (unsigned)dst >= NN) continue;

        const float4 bv = *(const float4*)(B + (size_t)e * H + cbase);
        const float4 pv = *(const float4*)(P + (size_t)src * H + cbase);

        float m0 = pv.x + bv.x, m1 = pv.y + bv.y;
        float m2 = pv.z + bv.z, m3 = pv.w + bv.w;
        m0 = fmaxf(m0, 0.1f * m0);
        m1 = fmaxf(m1, 0.1f * m1);
        m2 = fmaxf(m2, 0.1f * m2);
        m3 = fmaxf(m3, 0.1f * m3);

        float* dp = agg + (size_t)dst * H + cbase;
        asm volatile("red.global.add.v4.f32 [%0], {%1, %2, %3, %4};"
                     :: "l"(dp), "f"(m0), "f"(m1), "f"(m2), "f"(m3)
                     : "memory");
    }
}

// ---------------------------------------------------------------------------
// upd: out = concat(h, agg) @ W1(128x64) + b1
// ---------------------------------------------------------------------------
__global__ __launch_bounds__(256) void upd_kernel(const float* __restrict__ h,
                                                  const float* __restrict__ agg,
                                                  const float* __restrict__ w,
                                                  const float* __restrict__ b,
                                                  float* __restrict__ out) {
    __shared__ float sW[2 * H][H];   // 32768 B
    __shared__ float sA[32][2 * H];  // 16384 B, XOR-swizzled by (row&3)<<3
    for (int i = threadIdx.x; i < 2 * H * H; i += 256) sW[i >> 6][i & 63] = w[i];

    const int lane = threadIdx.x & 31, wid = threadIdx.x >> 5;
    const int nl = lane & 3, cg = lane >> 2;
    const int myn = wid * 4 + nl;
    const int swz = nl << 3;
    const float4 bb0 = *(const float4*)&b[cg * 8];
    const float4 bb1 = *(const float4*)&b[cg * 8 + 4];

    for (int tile = blockIdx.x; tile < NN / 32; tile += gridDim.x) {
        const int base = tile * 32;
        __syncthreads();
        for (int i = threadIdx.x; i < 32 * H; i += 256) {
            const int r = i >> 6, c = i & 63;
            const int s = (r & 3) << 3;
            sA[r][c ^ s]        = h[(size_t)base * H + i];
            sA[r][(c + 64) ^ s] = agg[(size_t)base * H + i];
        }
        __syncthreads();

        float acc[8] = {bb0.x, bb0.y, bb0.z, bb0.w, bb1.x, bb1.y, bb1.z, bb1.w};
#pragma unroll 8
        for (int k = 0; k < 2 * H; k++) {
            const float a = sA[myn][k ^ swz];
            const float4 w0 = *(const float4*)&sW[k][cg * 8];
            const float4 w1 = *(const float4*)&sW[k][cg * 8 + 4];
            acc[0] += a * w0.x; acc[1] += a * w0.y; acc[2] += a * w0.z; acc[3] += a * w0.w;
            acc[4] += a * w1.x; acc[5] += a * w1.y; acc[6] += a * w1.z; acc[7] += a * w1.w;
        }
        const size_t o = (size_t)(base + myn) * H + cg * 8;
        *(float4*)&out[o]     = make_float4(acc[0], acc[1], acc[2], acc[3]);
        *(float4*)&out[o + 4] = make_float4(acc[4], acc[5], acc[6], acc[7]);
    }
}

// ---------------------------------------------------------------------------
extern "C" void kernel_launch(void* const* d_in, const int* in_sizes, int n_in,
                              void* d_out, int out_size) {
    const float* x      = (const float*)d_in[0];   // [100000, 75]
    const int*   eidx   = (const int*)d_in[1];     // [2, 1600000] (int64 -> int32)
    const float* eattr  = (const float*)d_in[2];   // [1600000, 16]
    const float* proj_w = (const float*)d_in[3];
    const float* proj_b = (const float*)d_in[4];
    const float* u2w    = (const float*)d_in[5];   // [3, 80, 64]
    const float* u2b    = (const float*)d_in[6];
    const float* u1w    = (const float*)d_in[7];   // [3, 128, 64]
    const float* u1b    = (const float*)d_in[8];
    float*       out    = (float*)d_out;           // [100000, 64]

    float *hA, *hB, *P, *agg, *B;
    cudaGetSymbolAddress((void**)&hA, g_hA);
    cudaGetSymbolAddress((void**)&hB, g_hB);
    cudaGetSymbolAddress((void**)&P, g_P);
    cudaGetSymbolAddress((void**)&agg, g_agg);
    cudaGetSymbolAddress((void**)&B, g_B);

    proj_kernel<<<592, 256>>>(x, proj_w, proj_b, hA);

    for (int l = 0; l < 3; l++) {
        const float* hin = (l == 1) ? hB : hA;          // l0:A, l1:B, l2:A
        float* hout = (l == 0) ? hB : ((l == 1) ? hA : out);
        const float* w2 = u2w + (size_t)l * 80 * 64;     // rows 0..63 = W2h, 64..79 = W2e
        mm_kernel<<<1184, 256>>>(eattr, w2 + 64 * 64, B);
        pk_kernel<<<592, 256>>>(hin, w2, u2b + l * 64, P, agg);
        edge_kernel<<<1184, 256>>>(eidx, eidx + NE, B, P, agg);
        upd_kernel<<<592, 256>>>(hin, agg, u1w + (size_t)l * 128 * 64, u1b + l * 64, hout);
    }
}

// round 7
// speedup vs baseline: 1.4715x; 1.2626x over previous
#include <cuda_runtime.h>
#include <cuda_fp16.h>

#define NN 100000
#define NE 1600000
#define IND 75
#define H 64
#define HB 16

// Scratch (allocation-free rule: __device__ globals)
__device__ __align__(256) float  g_hA[NN * H];
__device__ __align__(256) float  g_hB[NN * H];
__device__ __align__(256) float  g_P[NN * H];
__device__ __align__(256) float  g_agg[NN * H];
__device__ __align__(256) __half g_B[3][(size_t)NE * H];   // eattr @ W2e, all 3 layers, fp16

// ---------------------------------------------------------------------------
// proj: out = x @ W(75x64) + b     (run once)
// ---------------------------------------------------------------------------
__global__ __launch_bounds__(256) void proj_kernel(const float* __restrict__ x,
                                                   const float* __restrict__ w,
                                                   const float* __restrict__ b,
                                                   float* __restrict__ out) {
    __shared__ float sW[IND][H];
    __shared__ float sA[32][IND + 1];
    for (int i = threadIdx.x; i < IND * H; i += 256) sW[i / H][i % H] = w[i];

    const int lane = threadIdx.x & 31, wid = threadIdx.x >> 5;
    const int nl = lane & 3, cg = lane >> 2;
    const int myn = wid * 4 + nl;
    const float4 bb0 = *(const float4*)&b[cg * 8];
    const float4 bb1 = *(const float4*)&b[cg * 8 + 4];

    for (int tile = blockIdx.x; tile < NN / 32; tile += gridDim.x) {
        const int base = tile * 32;
        __syncthreads();
        for (int i = threadIdx.x; i < 32 * IND; i += 256)
            sA[i / IND][i % IND] = x[(size_t)base * IND + i];
        __syncthreads();

        float acc[8] = {bb0.x, bb0.y, bb0.z, bb0.w, bb1.x, bb1.y, bb1.z, bb1.w};
#pragma unroll 5
        for (int k = 0; k < IND; k++) {
            const float a = sA[myn][k];
            const float4 w0 = *(const float4*)&sW[k][cg * 8];
            const float4 w1 = *(const float4*)&sW[k][cg * 8 + 4];
            acc[0] += a * w0.x; acc[1] += a * w0.y; acc[2] += a * w0.z; acc[3] += a * w0.w;
            acc[4] += a * w1.x; acc[5] += a * w1.y; acc[6] += a * w1.z; acc[7] += a * w1.w;
        }
        const size_t o = (size_t)(base + myn) * H + cg * 8;
        *(float4*)&out[o]     = make_float4(acc[0], acc[1], acc[2], acc[3]);
        *(float4*)&out[o + 4] = make_float4(acc[4], acc[5], acc[6], acc[7]);
    }
}

// ---------------------------------------------------------------------------
// pk: P = h @ W2h(64x64) + b2, and zero agg (fused).
// ---------------------------------------------------------------------------
__global__ __launch_bounds__(256) void pk_kernel(const float* __restrict__ h,
                                                 const float* __restrict__ w,
                                                 const float* __restrict__ b,
                                                 float* __restrict__ P,
                                                 float* __restrict__ agg) {
    __shared__ float sW[H][H];
    __shared__ float sA[32][H + 1];
    for (int i = threadIdx.x; i < H * H; i += 256) sW[i >> 6][i & 63] = w[i];

    const int lane = threadIdx.x & 31, wid = threadIdx.x >> 5;
    const int nl = lane & 3, cg = lane >> 2;
    const int myn = wid * 4 + nl;
    const float4 bb0 = *(const float4*)&b[cg * 8];
    const float4 bb1 = *(const float4*)&b[cg * 8 + 4];
    const float4 z4 = make_float4(0.f, 0.f, 0.f, 0.f);

    for (int tile = blockIdx.x; tile < NN / 32; tile += gridDim.x) {
        const int base = tile * 32;
        __syncthreads();
        for (int i = threadIdx.x; i < 32 * H; i += 256)
            sA[i >> 6][i & 63] = h[(size_t)base * H + i];
        __syncthreads();

        float acc[8] = {bb0.x, bb0.y, bb0.z, bb0.w, bb1.x, bb1.y, bb1.z, bb1.w};
#pragma unroll 8
        for (int k = 0; k < H; k++) {
            const float a = sA[myn][k];
            const float4 w0 = *(const float4*)&sW[k][cg * 8];
            const float4 w1 = *(const float4*)&sW[k][cg * 8 + 4];
            acc[0] += a * w0.x; acc[1] += a * w0.y; acc[2] += a * w0.z; acc[3] += a * w0.w;
            acc[4] += a * w1.x; acc[5] += a * w1.y; acc[6] += a * w1.z; acc[7] += a * w1.w;
        }
        const size_t o = (size_t)(base + myn) * H + cg * 8;
        *(float4*)&P[o]     = make_float4(acc[0], acc[1], acc[2], acc[3]);
        *(float4*)&P[o + 4] = make_float4(acc[4], acc[5], acc[6], acc[7]);
        *(float4*)&agg[o]     = z4;
        *(float4*)&agg[o + 4] = z4;
    }
}

// ---------------------------------------------------------------------------
// mm3: B[l] = eattr @ W2e_l (16x64), l = 0..2, fp16 output. Reads eattr ONCE.
// Tile pattern as proj: 32 edges/tile, warp=4 edges, thread=8 cols (all 3 layers).
// ---------------------------------------------------------------------------
__global__ __launch_bounds__(256) void mm3_kernel(const float* __restrict__ eattr,
                                                  const float* __restrict__ u2w,
                                                  __half* __restrict__ B0,
                                                  __half* __restrict__ B1,
                                                  __half* __restrict__ B2) {
    __shared__ float sW[3][HB][H];     // 12288 B
    __shared__ float sA[32][HB + 1];   // 2176 B
    for (int i = threadIdx.x; i < 3 * HB * H; i += 256) {
        const int l = i >> 10, r = i & 1023;
        sW[l][r >> 6][r & 63] = u2w[(size_t)l * 80 * 64 + 64 * 64 + r];
    }

    const int lane = threadIdx.x & 31, wid = threadIdx.x >> 5;
    const int nl = lane & 3, cg = lane >> 2;
    const int myn = wid * 4 + nl;
    __half* const Bs[3] = {B0, B1, B2};

    for (int tile = blockIdx.x; tile < NE / 32; tile += gridDim.x) {
        const int base = tile * 32;
        __syncthreads();
        for (int i = threadIdx.x; i < 32 * HB; i += 256)
            sA[i >> 4][i & 15] = eattr[(size_t)base * HB + i];
        __syncthreads();

        float acc[3][8];
#pragma unroll
        for (int l = 0; l < 3; l++)
#pragma unroll
            for (int c = 0; c < 8; c++) acc[l][c] = 0.f;

#pragma unroll
        for (int k = 0; k < HB; k++) {
            const float a = sA[myn][k];
#pragma unroll
            for (int l = 0; l < 3; l++) {
                const float4 w0 = *(const float4*)&sW[l][k][cg * 8];
                const float4 w1 = *(const float4*)&sW[l][k][cg * 8 + 4];
                acc[l][0] += a * w0.x; acc[l][1] += a * w0.y;
                acc[l][2] += a * w0.z; acc[l][3] += a * w0.w;
                acc[l][4] += a * w1.x; acc[l][5] += a * w1.y;
                acc[l][6] += a * w1.z; acc[l][7] += a * w1.w;
            }
        }
        const size_t o = (size_t)(base + myn) * H + cg * 8;
#pragma unroll
        for (int l = 0; l < 3; l++) {
            __half2 h0 = __floats2half2_rn(acc[l][0], acc[l][1]);
            __half2 h1 = __floats2half2_rn(acc[l][2], acc[l][3]);
            __half2 h2 = __floats2half2_rn(acc[l][4], acc[l][5]);
            __half2 h3 = __floats2half2_rn(acc[l][6], acc[l][7]);
            uint4 pk;
            pk.x = *(unsigned*)&h0; pk.y = *(unsigned*)&h1;
            pk.z = *(unsigned*)&h2; pk.w = *(unsigned*)&h3;
            *(uint4*)(Bs[l] + o) = pk;
        }
    }
}

// ---------------------------------------------------------------------------
// edge: agg[dst] +=red leakyrelu(P[src] + B[e]).  B in fp16.
// Half-warp per edge, lane owns 4 cols. Zero MIO, full occupancy.
// ---------------------------------------------------------------------------
__global__ __launch_bounds__(256) void edge_kernel(const int* __restrict__ esrc,
                                                   const int* __restrict__ edst,
                                                   const __half* __restrict__ B,
                                                   const float* __restrict__ P,
                                                   float* __restrict__ agg) {
    const int lane = threadIdx.x & 31;
    const int half = lane >> 4, hl = lane & 15;
    const int cbase = hl * 4;

    const int gw = blockIdx.x * 8 + (threadIdx.x >> 5);
    const int nw = gridDim.x * 8;

    for (int p = gw; p < NE / 2; p += nw) {
        const int e = 2 * p + half;
        const int src = esrc[e];
        const int dst = edst[e];
        if ((unsigned)src >= NN || (unsigned)dst >= NN) continue;

        const uint2 braw = *(const uint2*)(B + (size_t)e * H + cbase);
        const float2 b0 = __half22float2(*(const __half2*)&braw.x);
        const float2 b1 = __half22float2(*(const __half2*)&braw.y);
        const float4 pv = *(const float4*)(P + (size_t)src * H + cbase);

        float m0 = pv.x + b0.x, m1 = pv.y + b0.y;
        float m2 = pv.z + b1.x, m3 = pv.w + b1.y;
        m0 = fmaxf(m0, 0.1f * m0);
        m1 = fmaxf(m1, 0.1f * m1);
        m2 = fmaxf(m2, 0.1f * m2);
        m3 = fmaxf(m3, 0.1f * m3);

        float* dp = agg + (size_t)dst * H + cbase;
        asm volatile("red.global.add.v4.f32 [%0], {%1, %2, %3, %4};"
                     :: "l"(dp), "f"(m0), "f"(m1), "f"(m2), "f"(m3)
                     : "memory");
    }
}

// ---------------------------------------------------------------------------
// upd: out = concat(h, agg) @ W1(128x64) + b1
// ---------------------------------------------------------------------------
__global__ __launch_bounds__(256) void upd_kernel(const float* __restrict__ h,
                                                  const float* __restrict__ agg,
                                                  const float* __restrict__ w,
                                                  const float* __restrict__ b,
                                                  float* __restrict__ out) {
    __shared__ float sW[2 * H][H];   // 32768 B
    __shared__ float sA[32][2 * H];  // 16384 B, XOR-swizzled by (row&3)<<3
    for (int i = threadIdx.x; i < 2 * H * H; i += 256) sW[i >> 6][i & 63] = w[i];

    const int lane = threadIdx.x & 31, wid = threadIdx.x >> 5;
    const int nl = lane & 3, cg = lane >> 2;
    const int myn = wid * 4 + nl;
    const int swz = nl << 3;
    const float4 bb0 = *(const float4*)&b[cg * 8];
    const float4 bb1 = *(const float4*)&b[cg * 8 + 4];

    for (int tile = blockIdx.x; tile < NN / 32; tile += gridDim.x) {
        const int base = tile * 32;
        __syncthreads();
        for (int i = threadIdx.x; i < 32 * H; i += 256) {
            const int r = i >> 6, c = i & 63;
            const int s = (r & 3) << 3;
            sA[r][c ^ s]        = h[(size_t)base * H + i];
            sA[r][(c + 64) ^ s] = agg[(size_t)base * H + i];
        }
        __syncthreads();

        float acc[8] = {bb0.x, bb0.y, bb0.z, bb0.w, bb1.x, bb1.y, bb1.z, bb1.w};
#pragma unroll 8
        for (int k = 0; k < 2 * H; k++) {
            const float a = sA[myn][k ^ swz];
            const float4 w0 = *(const float4*)&sW[k][cg * 8];
            const float4 w1 = *(const float4*)&sW[k][cg * 8 + 4];
            acc[0] += a * w0.x; acc[1] += a * w0.y; acc[2] += a * w0.z; acc[3] += a * w0.w;
            acc[4] += a * w1.x; acc[5] += a * w1.y; acc[6] += a * w1.z; acc[7] += a * w1.w;
        }
        const size_t o = (size_t)(base + myn) * H + cg * 8;
        *(float4*)&out[o]     = make_float4(acc[0], acc[1], acc[2], acc[3]);
        *(float4*)&out[o + 4] = make_float4(acc[4], acc[5], acc[6], acc[7]);
    }
}

// ---------------------------------------------------------------------------
extern "C" void kernel_launch(void* const* d_in, const int* in_sizes, int n_in,
                              void* d_out, int out_size) {
    const float* x      = (const float*)d_in[0];   // [100000, 75]
    const int*   eidx   = (const int*)d_in[1];     // [2, 1600000] (int64 -> int32)
    const float* eattr  = (const float*)d_in[2];   // [1600000, 16]
    const float* proj_w = (const float*)d_in[3];
    const float* proj_b = (const float*)d_in[4];
    const float* u2w    = (const float*)d_in[5];   // [3, 80, 64]
    const float* u2b    = (const float*)d_in[6];
    const float* u1w    = (const float*)d_in[7];   // [3, 128, 64]
    const float* u1b    = (const float*)d_in[8];
    float*       out    = (float*)d_out;           // [100000, 64]

    float *hA, *hB, *P, *agg;
    __half* B;
    cudaGetSymbolAddress((void**)&hA, g_hA);
    cudaGetSymbolAddress((void**)&hB, g_hB);
    cudaGetSymbolAddress((void**)&P, g_P);
    cudaGetSymbolAddress((void**)&agg, g_agg);
    cudaGetSymbolAddress((void**)&B, g_B);
    __half* B0 = B;
    __half* B1 = B + (size_t)NE * H;
    __half* B2 = B + 2 * (size_t)NE * H;

    proj_kernel<<<592, 256>>>(x, proj_w, proj_b, hA);
    mm3_kernel<<<1184, 256>>>(eattr, u2w, B0, B1, B2);

    const __half* Bs[3] = {B0, B1, B2};
    for (int l = 0; l < 3; l++) {
        const float* hin = (l == 1) ? hB : hA;          // l0:A, l1:B, l2:A
        float* hout = (l == 0) ? hB : ((l == 1) ? hA : out);
        const float* w2 = u2w + (size_t)l * 80 * 64;     // rows 0..63 = W2h
        pk_kernel<<<592, 256>>>(hin, w2, u2b + l * 64, P, agg);
        edge_kernel<<<1184, 256>>>(eidx, eidx + NE, Bs[l], P, agg);
        upd_kernel<<<592, 256>>>(hin, agg, u1w + (size_t)l * 128 * 64, u1b + l * 64, hout);
    }
}

// round 8
// speedup vs baseline: 2.0744x; 1.4098x over previous
#include <cuda_runtime.h>
#include <cuda_fp16.h>
#include <mma.h>

using namespace nvcuda;

#define NN 100000
#define NE 1600000
#define IND 75
#define H 64
#define HB 16

// Scratch (allocation-free rule: __device__ globals)
__device__ __align__(256) float g_hA[NN * H];
__device__ __align__(256) float g_hB[NN * H];
__device__ __align__(256) float g_P[NN * H];
__device__ __align__(256) float g_agg[NN * H];

// ---------------------------------------------------------------------------
// proj: out = x @ W(75x64) + b     (run once)
// ---------------------------------------------------------------------------
__global__ __launch_bounds__(256) void proj_kernel(const float* __restrict__ x,
                                                   const float* __restrict__ w,
                                                   const float* __restrict__ b,
                                                   float* __restrict__ out) {
    __shared__ float sW[IND][H];
    __shared__ float sA[32][IND + 1];
    for (int i = threadIdx.x; i < IND * H; i += 256) sW[i / H][i % H] = w[i];

    const int lane = threadIdx.x & 31, wid = threadIdx.x >> 5;
    const int nl = lane & 3, cg = lane >> 2;
    const int myn = wid * 4 + nl;
    const float4 bb0 = *(const float4*)&b[cg * 8];
    const float4 bb1 = *(const float4*)&b[cg * 8 + 4];

    for (int tile = blockIdx.x; tile < NN / 32; tile += gridDim.x) {
        const int base = tile * 32;
        __syncthreads();
        for (int i = threadIdx.x; i < 32 * IND; i += 256)
            sA[i / IND][i % IND] = x[(size_t)base * IND + i];
        __syncthreads();

        float acc[8] = {bb0.x, bb0.y, bb0.z, bb0.w, bb1.x, bb1.y, bb1.z, bb1.w};
#pragma unroll 5
        for (int k = 0; k < IND; k++) {
            const float a = sA[myn][k];
            const float4 w0 = *(const float4*)&sW[k][cg * 8];
            const float4 w1 = *(const float4*)&sW[k][cg * 8 + 4];
            acc[0] += a * w0.x; acc[1] += a * w0.y; acc[2] += a * w0.z; acc[3] += a * w0.w;
            acc[4] += a * w1.x; acc[5] += a * w1.y; acc[6] += a * w1.z; acc[7] += a * w1.w;
        }
        const size_t o = (size_t)(base + myn) * H + cg * 8;
        *(float4*)&out[o]     = make_float4(acc[0], acc[1], acc[2], acc[3]);
        *(float4*)&out[o + 4] = make_float4(acc[4], acc[5], acc[6], acc[7]);
    }
}

// ---------------------------------------------------------------------------
// pk: P = h @ W2h(64x64) + b2, and zero agg (fused).
// ---------------------------------------------------------------------------
__global__ __launch_bounds__(256) void pk_kernel(const float* __restrict__ h,
                                                 const float* __restrict__ w,
                                                 const float* __restrict__ b,
                                                 float* __restrict__ P,
                                                 float* __restrict__ agg) {
    __shared__ float sW[H][H];
    __shared__ float sA[32][H + 1];
    for (int i = threadIdx.x; i < H * H; i += 256) sW[i >> 6][i & 63] = w[i];

    const int lane = threadIdx.x & 31, wid = threadIdx.x >> 5;
    const int nl = lane & 3, cg = lane >> 2;
    const int myn = wid * 4 + nl;
    const float4 bb0 = *(const float4*)&b[cg * 8];
    const float4 bb1 = *(const float4*)&b[cg * 8 + 4];
    const float4 z4 = make_float4(0.f, 0.f, 0.f, 0.f);

    for (int tile = blockIdx.x; tile < NN / 32; tile += gridDim.x) {
        const int base = tile * 32;
        __syncthreads();
        for (int i = threadIdx.x; i < 32 * H; i += 256)
            sA[i >> 6][i & 63] = h[(size_t)base * H + i];
        __syncthreads();

        float acc[8] = {bb0.x, bb0.y, bb0.z, bb0.w, bb1.x, bb1.y, bb1.z, bb1.w};
#pragma unroll 8
        for (int k = 0; k < H; k++) {
            const float a = sA[myn][k];
            const float4 w0 = *(const float4*)&sW[k][cg * 8];
            const float4 w1 = *(const float4*)&sW[k][cg * 8 + 4];
            acc[0] += a * w0.x; acc[1] += a * w0.y; acc[2] += a * w0.z; acc[3] += a * w0.w;
            acc[4] += a * w1.x; acc[5] += a * w1.y; acc[6] += a * w1.z; acc[7] += a * w1.w;
        }
        const size_t o = (size_t)(base + myn) * H + cg * 8;
        *(float4*)&P[o]     = make_float4(acc[0], acc[1], acc[2], acc[3]);
        *(float4*)&P[o + 4] = make_float4(acc[4], acc[5], acc[6], acc[7]);
        *(float4*)&agg[o]     = z4;
        *(float4*)&agg[o + 4] = z4;
    }
}

// ---------------------------------------------------------------------------
// edge v5: fused HMMA edge kernel. Warp handles 16 consecutive edges:
//   1. load eattr[16x16] fp32 -> fp16 smem tile (2 LDG.128 + 1 STS.128/lane)
//   2. 4x wmma m16n16k16 (fp16 in, fp32 acc) against register-resident W2e
//   3. result tile [16x64] fp32 in smem
//   4. scatter: half-warp per edge: agg[dst] +=red leakyrelu(P[src] + Brow)
// B never touches global memory. No separate mm pass.
// ---------------------------------------------------------------------------
__global__ __launch_bounds__(256) void edge_kernel(const int* __restrict__ esrc,
                                                   const int* __restrict__ edst,
                                                   const float* __restrict__ eattr,
                                                   const float* __restrict__ w2e,
                                                   const float* __restrict__ P,
                                                   float* __restrict__ agg) {
    __shared__ __half sW[HB * H];              // 2048 B, row-major [16][64]
    __shared__ __half sA[8][HB * HB];          // 8 x 512 B, per-warp [16][16]
    __shared__ float  sB[8][HB * H];           // 8 x 4096 B, per-warp [16][64]

    for (int i = threadIdx.x; i < HB * H; i += 256) sW[i] = __float2half(w2e[i]);
    __syncthreads();

    const int lane = threadIdx.x & 31, wid = threadIdx.x >> 5;
    const int half = lane >> 4, hl = lane & 15;
    const int cbase = hl * 4;

    // W2e fragments live in registers for the whole kernel.
    wmma::fragment<wmma::matrix_b, 16, 16, 16, __half, wmma::row_major> fw[4];
#pragma unroll
    for (int nt = 0; nt < 4; nt++)
        wmma::load_matrix_sync(fw[nt], &sW[nt * 16], H);

    __half* const myA = sA[wid];
    float*  const myB = sB[wid];

    // eattr staging coords: lane covers 8 floats of row (lane>>1), half-row (lane&1)
    const int arow = lane >> 1, acol = (lane & 1) * 8;

    const int gw = blockIdx.x * 8 + wid;
    const int nw = gridDim.x * 8;

    for (int t = gw; t < NE / 16; t += nw) {
        const int ebase = t * 16;

        // 1. stage eattr tile as fp16
        {
            const float4* src = (const float4*)(eattr + (size_t)(ebase + arow) * HB + acol);
            const float4 v0 = src[0], v1 = src[1];
            __half2 h0 = __floats2half2_rn(v0.x, v0.y);
            __half2 h1 = __floats2half2_rn(v0.z, v0.w);
            __half2 h2 = __floats2half2_rn(v1.x, v1.y);
            __half2 h3 = __floats2half2_rn(v1.z, v1.w);
            uint4 pk;
            pk.x = *(unsigned*)&h0; pk.y = *(unsigned*)&h1;
            pk.z = *(unsigned*)&h2; pk.w = *(unsigned*)&h3;
            *(uint4*)(myA + arow * HB + acol) = pk;
        }
        __syncwarp();

        // 2-3. HMMA: [16x16] @ [16x64] -> smem fp32
        wmma::fragment<wmma::matrix_a, 16, 16, 16, __half, wmma::row_major> fa;
        wmma::load_matrix_sync(fa, myA, HB);
#pragma unroll
        for (int nt = 0; nt < 4; nt++) {
            wmma::fragment<wmma::accumulator, 16, 16, 16, float> fc;
            wmma::fill_fragment(fc, 0.f);
            wmma::mma_sync(fc, fa, fw[nt], fc);
            wmma::store_matrix_sync(&myB[nt * 16], fc, H, wmma::mem_row_major);
        }
        __syncwarp();

        // 4. scatter: 8 iterations, 2 edges each (one per half-warp)
#pragma unroll
        for (int r = 0; r < 8; r++) {
            const int el = 2 * r + half;
            const int e = ebase + el;
            const int src = esrc[e];
            const int dst = edst[e];
            if ((unsigned)src >= NN || (unsigned)dst >= NN) continue;

            const float4 bv = *(const float4*)(myB + el * H + cbase);
            const float4 pv = *(const float4*)(P + (size_t)src * H + cbase);

            float m0 = pv.x + bv.x, m1 = pv.y + bv.y;
            float m2 = pv.z + bv.z, m3 = pv.w + bv.w;
            m0 = fmaxf(m0, 0.1f * m0);
            m1 = fmaxf(m1, 0.1f * m1);
            m2 = fmaxf(m2, 0.1f * m2);
            m3 = fmaxf(m3, 0.1f * m3);

            float* dp = agg + (size_t)dst * H + cbase;
            asm volatile("red.global.add.v4.f32 [%0], {%1, %2, %3, %4};"
                         :: "l"(dp), "f"(m0), "f"(m1), "f"(m2), "f"(m3)
                         : "memory");
        }
        __syncwarp();
    }
}

// ---------------------------------------------------------------------------
// upd: out = concat(h, agg) @ W1(128x64) + b1
// ---------------------------------------------------------------------------
__global__ __launch_bounds__(256) void upd_kernel(const float* __restrict__ h,
                                                  const float* __restrict__ agg,
                                                  const float* __restrict__ w,
                                                  const float* __restrict__ b,
                                                  float* __restrict__ out) {
    __shared__ float sW[2 * H][H];   // 32768 B
    __shared__ float sA[32][2 * H];  // 16384 B, XOR-swizzled by (row&3)<<3
    for (int i = threadIdx.x; i < 2 * H * H; i += 256) sW[i >> 6][i & 63] = w[i];

    const int lane = threadIdx.x & 31, wid = threadIdx.x >> 5;
    const int nl = lane & 3, cg = lane >> 2;
    const int myn = wid * 4 + nl;
    const int swz = nl << 3;
    const float4 bb0 = *(const float4*)&b[cg * 8];
    const float4 bb1 = *(const float4*)&b[cg * 8 + 4];

    for (int tile = blockIdx.x; tile < NN / 32; tile += gridDim.x) {
        const int base = tile * 32;
        __syncthreads();
        for (int i = threadIdx.x; i < 32 * H; i += 256) {
            const int r = i >> 6, c = i & 63;
            const int s = (r & 3) << 3;
            sA[r][c ^ s]        = h[(size_t)base * H + i];
            sA[r][(c + 64) ^ s] = agg[(size_t)base * H + i];
        }
        __syncthreads();

        float acc[8] = {bb0.x, bb0.y, bb0.z, bb0.w, bb1.x, bb1.y, bb1.z, bb1.w};
#pragma unroll 8
        for (int k = 0; k < 2 * H; k++) {
            const float a = sA[myn][k ^ swz];
            const float4 w0 = *(const float4*)&sW[k][cg * 8];
            const float4 w1 = *(const float4*)&sW[k][cg * 8 + 4];
            acc[0] += a * w0.x; acc[1] += a * w0.y; acc[2] += a * w0.z; acc[3] += a * w0.w;
            acc[4] += a * w1.x; acc[5] += a * w1.y; acc[6] += a * w1.z; acc[7] += a * w1.w;
        }
        const size_t o = (size_t)(base + myn) * H + cg * 8;
        *(float4*)&out[o]     = make_float4(acc[0], acc[1], acc[2], acc[3]);
        *(float4*)&out[o + 4] = make_float4(acc[4], acc[5], acc[6], acc[7]);
    }
}

// ---------------------------------------------------------------------------
extern "C" void kernel_launch(void* const* d_in, const int* in_sizes, int n_in,
                              void* d_out, int out_size) {
    const float* x      = (const float*)d_in[0];   // [100000, 75]
    const int*   eidx   = (const int*)d_in[1];     // [2, 1600000] (int64 -> int32)
    const float* eattr  = (const float*)d_in[2];   // [1600000, 16]
    const float* proj_w = (const float*)d_in[3];
    const float* proj_b = (const float*)d_in[4];
    const float* u2w    = (const float*)d_in[5];   // [3, 80, 64]
    const float* u2b    = (const float*)d_in[6];
    const float* u1w    = (const float*)d_in[7];   // [3, 128, 64]
    const float* u1b    = (const float*)d_in[8];
    float*       out    = (float*)d_out;           // [100000, 64]

    float *hA, *hB, *P, *agg;
    cudaGetSymbolAddress((void**)&hA, g_hA);
    cudaGetSymbolAddress((void**)&hB, g_hB);
    cudaGetSymbolAddress((void**)&P, g_P);
    cudaGetSymbolAddress((void**)&agg, g_agg);

    proj_kernel<<<592, 256>>>(x, proj_w, proj_b, hA);

    for (int l = 0; l < 3; l++) {
        const float* hin = (l == 1) ? hB : hA;          // l0:A, l1:B, l2:A
        float* hout = (l == 0) ? hB : ((l == 1) ? hA : out);
        const float* w2 = u2w + (size_t)l * 80 * 64;     // rows 0..63 = W2h, 64..79 = W2e
        pk_kernel<<<592, 256>>>(hin, w2, u2b + l * 64, P, agg);
        edge_kernel<<<1184, 256>>>(eidx, eidx + NE, eattr, w2 + 64 * 64, P, agg);
        upd_kernel<<<592, 256>>>(hin, agg, u1w + (size_t)l * 128 * 64, u1b + l * 64, hout);
    }
}